// round 8
// baseline (speedup 1.0000x reference)
#include <cuda_runtime.h>
#include <cuda_fp16.h>
#include <cstdint>

// Problem constants
#define B_  4
#define S_  2048
#define D_  1024
#define H_  16
#define HD_ 64
#define M_  (B_ * S_)
#define OUT_ELEMS ((size_t)B_ * S_ * D_)

// Scratch
__device__ float g_qh[OUT_ELEMS];
__device__ float g_attn[OUT_ELEMS];

__device__ __forceinline__ uint32_t smem_u32(const void* p) {
    uint32_t a;
    asm("{ .reg .u64 t; cvta.to.shared.u64 t, %1; cvt.u32.u64 %0, t; }" : "=r"(a) : "l"(p));
    return a;
}
__device__ __forceinline__ uint32_t sw128(uint32_t off) { return off ^ ((off >> 3) & 0x70); }

__device__ __forceinline__ void ldsm_x4(uint32_t* r, uint32_t addr) {
    asm volatile("ldmatrix.sync.aligned.m8n8.x4.shared.b16 {%0,%1,%2,%3}, [%4];"
        : "=r"(r[0]), "=r"(r[1]), "=r"(r[2]), "=r"(r[3]) : "r"(addr));
}
__device__ __forceinline__ void mma_f16(float* d, const uint32_t* a, const uint32_t* b) {
    asm volatile(
        "mma.sync.aligned.m16n8k16.row.col.f32.f16.f16.f32 "
        "{%0,%1,%2,%3}, {%4,%5,%6,%7}, {%8,%9}, {%0,%1,%2,%3};"
        : "+f"(d[0]), "+f"(d[1]), "+f"(d[2]), "+f"(d[3])
        : "r"(a[0]), "r"(a[1]), "r"(a[2]), "r"(a[3]), "r"(b[0]), "r"(b[1]));
}

// split 4 floats -> hi/lo fp16 packed pairs
__device__ __forceinline__ void split4(const float* f, uint2* hi, uint2* lo) {
    __half h0 = __float2half_rn(f[0]), h1 = __float2half_rn(f[1]);
    __half h2 = __float2half_rn(f[2]), h3 = __float2half_rn(f[3]);
    __half l0 = __float2half_rn(f[0] - __half2float(h0));
    __half l1 = __float2half_rn(f[1] - __half2float(h1));
    __half l2 = __float2half_rn(f[2] - __half2float(h2));
    __half l3 = __float2half_rn(f[3] - __half2float(h3));
    hi->x = (uint32_t)__half_as_ushort(h0) | ((uint32_t)__half_as_ushort(h1) << 16);
    hi->y = (uint32_t)__half_as_ushort(h2) | ((uint32_t)__half_as_ushort(h3) << 16);
    lo->x = (uint32_t)__half_as_ushort(l0) | ((uint32_t)__half_as_ushort(l1) << 16);
    lo->y = (uint32_t)__half_as_ushort(l2) | ((uint32_t)__half_as_ushort(l3) << 16);
}
__device__ __forceinline__ uint32_t packh2(float a, float b) {
    return (uint32_t)__half_as_ushort(__float2half_rn(a)) |
           ((uint32_t)__half_as_ushort(__float2half_rn(b)) << 16);
}
__device__ __forceinline__ float h2lo_res(uint32_t h, float a) {
    return a - __half2float(__ushort_as_half((unsigned short)(h & 0xffff)));
}

__device__ __forceinline__ void split_store(char* smem_hi_base, uint32_t off, float4 v) {
    float f[4] = {v.x, v.y, v.z, v.w};
    uint2 hi, lo;
    split4(f, &hi, &lo);
    *(uint2*)(smem_hi_base + off)         = hi;
    *(uint2*)(smem_hi_base + 16384 + off) = lo;
}

// ============================================================================
// Pipelined HMMA GEMM: C[M,N] = A[M,K] @ W[N,K]^T + bias.
// Tile 128x128, BK=64, 512 threads (16 warps 4x4, 32x32/warp).
// Double-buffered smem (2 x 64KB), register prefetch of next chunk.
// Stage s: AHI@s*64K, ALO+16K, BHI+32K, BLO+48K.
// ============================================================================
#define GEMM_SMEM 131072
#define STAGE 65536

__global__ __launch_bounds__(512, 1) void gemm_hmma_kernel(
    const float* __restrict__ A0, const float* __restrict__ A1, const float* __restrict__ A2,
    const float* __restrict__ W0, const float* __restrict__ W1, const float* __restrict__ W2,
    const float* __restrict__ bi0, const float* __restrict__ bi1, const float* __restrict__ bi2,
    float* __restrict__ C0, float* __restrict__ C1, float* __restrict__ C2, int mode)
{
    extern __shared__ char sm[];
    const uint32_t smb = smem_u32(sm);
    const int tid = threadIdx.x;
    const int lane = tid & 31;
    const int wid = tid >> 5;
    const int wm = wid >> 2;           // 0..3 -> 32 rows each
    const int wn = wid & 3;            // 0..3 -> 32 cols each
    const int z = blockIdx.z;
    const float* A = (z == 0) ? A0 : (z == 1) ? A1 : A2;
    const float* W = (z == 0) ? W0 : (z == 1) ? W1 : W2;
    const float* bias = (z == 0) ? bi0 : (z == 1) ? bi1 : bi2;
    float* C = (z == 0) ? C0 : (z == 1) ? C1 : C2;

    const int m0 = blockIdx.y * 128;
    const int n0 = blockIdx.x * 128;

    float acc[2][4][4];
    #pragma unroll
    for (int i = 0; i < 2; i++)
        #pragma unroll
        for (int j = 0; j < 4; j++)
            #pragma unroll
            for (int t = 0; t < 4; t++) acc[i][j][t] = 0.f;

    // ldmatrix lane components (proven mapping)
    const int a_m = lane & 15;
    const int a_kb = (lane >> 4) * 16;
    const int b_n = (lane & 7) + ((lane >> 4) & 1) * 8;
    const int b_kb = ((lane >> 3) & 1) * 16;

    // loader: 512 threads, each 4 float4 per matrix per chunk
    const int lrow = tid >> 2;           // 0..127
    const int lc0 = (tid & 3) * 16;      // 0,16,32,48 (fp32 col base)
    const float* aptr = A + (size_t)(m0 + lrow) * D_ + lc0;
    const float* wptr = W + (size_t)(n0 + lrow) * D_ + lc0;

    float4 ra[4], rw[4];
    // prologue: load chunk 0, store to stage 0
    #pragma unroll
    for (int i = 0; i < 4; i++) {
        ra[i] = *(const float4*)(aptr + i * 4);
        rw[i] = *(const float4*)(wptr + i * 4);
    }
    #pragma unroll
    for (int i = 0; i < 4; i++) {
        uint32_t off = sw128((uint32_t)(lrow * 128 + (lc0 + i * 4) * 2));
        split_store(sm, off, ra[i]);
        split_store(sm + 32768, off, rw[i]);
    }
    __syncthreads();

    for (int c = 0; c < 16; c++) {
        // prefetch next chunk into registers (LDG latency hidden by MMAs)
        if (c < 15) {
            const int knext = (c + 1) * 64;
            #pragma unroll
            for (int i = 0; i < 4; i++) {
                ra[i] = *(const float4*)(aptr + knext + i * 4);
                rw[i] = *(const float4*)(wptr + knext + i * 4);
            }
        }

        // MMAs on stage c&1
        const uint32_t sbase = smb + (uint32_t)(c & 1) * STAGE;
        #pragma unroll
        for (int ks = 0; ks < 4; ks++) {
            uint32_t afh[2][4], afl[2][4];
            #pragma unroll
            for (int mt = 0; mt < 2; mt++) {
                uint32_t byte = (uint32_t)((wm * 32 + mt * 16 + a_m) * 128 + ks * 32 + a_kb);
                uint32_t ad = sbase + sw128(byte);
                ldsm_x4(afh[mt], ad);
                ldsm_x4(afl[mt], ad + 16384);
            }
            uint32_t bfh[2][4], bfl[2][4];
            #pragma unroll
            for (int bt = 0; bt < 2; bt++) {
                uint32_t byte = (uint32_t)((wn * 32 + bt * 16 + b_n) * 128 + ks * 32 + b_kb);
                uint32_t bd = sbase + 32768 + sw128(byte);
                ldsm_x4(bfh[bt], bd);
                ldsm_x4(bfl[bt], bd + 16384);
            }
            #pragma unroll
            for (int mt = 0; mt < 2; mt++)
                #pragma unroll
                for (int nt = 0; nt < 4; nt++) {
                    const uint32_t* bh = &bfh[nt >> 1][(nt & 1) * 2];
                    const uint32_t* bl = &bfl[nt >> 1][(nt & 1) * 2];
                    mma_f16(acc[mt][nt], afh[mt], bh);
                    mma_f16(acc[mt][nt], afh[mt], bl);
                    mma_f16(acc[mt][nt], afl[mt], bh);
                }
        }

        // convert + store prefetched chunk to the other stage
        if (c < 15) {
            char* dst = sm + ((c + 1) & 1) * STAGE;
            #pragma unroll
            for (int i = 0; i < 4; i++) {
                uint32_t off = sw128((uint32_t)(lrow * 128 + (lc0 + i * 4) * 2));
                split_store(dst, off, ra[i]);
                split_store(dst + 32768, off, rw[i]);
            }
            __syncthreads();
        }
    }

    // Epilogue
    const int g = lane >> 2;
    const int q2 = (lane & 3) * 2;
    #pragma unroll
    for (int mt = 0; mt < 2; mt++) {
        #pragma unroll
        for (int nt = 0; nt < 4; nt++) {
            int mr = m0 + wm * 32 + mt * 16 + g;
            int nc = n0 + wn * 32 + nt * 8 + q2;
            float2 b2 = *(const float2*)(bias + nc);
            #pragma unroll
            for (int half = 0; half < 2; half++) {
                int m = mr + half * 8;
                float2 o = make_float2(acc[mt][nt][half * 2 + 0] + b2.x,
                                       acc[mt][nt][half * 2 + 1] + b2.y);
                float* dst;
                if (mode == 0) {
                    dst = C + (size_t)m * D_ + nc;
                } else {
                    int b = m >> 11, s = m & 2047, h = nc >> 6, hd = nc & 63;
                    dst = C + (((size_t)(b * H_ + h) * S_ + s) << 6) + hd;
                }
                *(float2*)dst = o;
            }
        }
    }
}

// ============================================================================
// Flash attention with HMMA (unchanged from round 7 — measured ~515us)
// ============================================================================
#define F_QHI 0
#define F_QLO 16384
#define F_KHI 32768
#define F_KLO 40960
#define F_VHI 49152
#define F_VLO 58368
#define VT_PITCH 144
#define FLASH_SMEM (F_VLO + 9216)   // 67584

__global__ __launch_bounds__(256, 2) void flash_kernel(
    const float* __restrict__ Qh, const float* __restrict__ Kh,
    const float* __restrict__ Vh, float* __restrict__ Out)
{
    extern __shared__ char smc[];
    const uint32_t smb = smem_u32(smc);
    const int tid = threadIdx.x;
    const int lane = tid & 31;
    const int w = tid >> 5;
    const int g = lane >> 2;
    const int q = lane & 3;
    const int bh = blockIdx.y;
    const int qblk = (int)gridDim.x - 1 - (int)blockIdx.x;
    const int q0 = qblk * 128;

    const float* Qbase = Qh + ((size_t)bh * S_ + q0) * HD_;
    const float* Kbase = Kh + (size_t)bh * S_ * HD_;
    const float* Vbase = Vh + (size_t)bh * S_ * HD_;

    {
        const int lrow = tid >> 4;
        const int lc4 = (tid & 15) * 4;
        #pragma unroll
        for (int i = 0; i < 8; i++) {
            int row = lrow + i * 16;
            float4 v = *(const float4*)(Qbase + (size_t)row * HD_ + lc4);
            float f[4] = {v.x, v.y, v.z, v.w};
            uint2 hi, lo;
            split4(f, &hi, &lo);
            uint32_t off = sw128((uint32_t)(row * 128 + lc4 * 2));
            *(uint2*)(smc + F_QHI + off) = hi;
            *(uint2*)(smc + F_QLO + off) = lo;
        }
    }

    float m_st[2] = {-1e30f, -1e30f};
    float l_st[2] = {0.f, 0.f};
    float o[8][4];
    #pragma unroll
    for (int t = 0; t < 8; t++)
        #pragma unroll
        for (int e = 0; e < 4; e++) o[t][e] = 0.f;

    const int a_m = lane & 15;
    const int a_kb = (lane >> 4) * 16;
    const int b_n = (lane & 7) + ((lane >> 4) & 1) * 8;
    const int b_kb = ((lane >> 3) & 1) * 16;
    const int v_row = (lane & 7) + ((lane >> 4) & 1) * 8;
    const int v_cb = ((lane >> 3) & 1) * 16;

    const int nkb = 2 * qblk + 2;
    for (int kb = 0; kb < nkb; kb++) {
        const int k0 = kb * 64;
        __syncthreads();
        {
            const int j = tid >> 2;
            const int c4 = (tid & 3) * 16;
            #pragma unroll
            for (int i = 0; i < 4; i++) {
                int cc = c4 + i * 4;
                float4 v = *(const float4*)(Kbase + (size_t)(k0 + j) * HD_ + cc);
                float f[4] = {v.x, v.y, v.z, v.w};
                uint2 hi, lo;
                split4(f, &hi, &lo);
                uint32_t off = sw128((uint32_t)(j * 128 + cc * 2));
                *(uint2*)(smc + F_KHI + off) = hi;
                *(uint2*)(smc + F_KLO + off) = lo;
            }
        }
        {
            const int d0 = (tid & 15) * 4;
            const int j0 = (tid >> 4) * 4;
            float4 vv[4];
            #pragma unroll
            for (int jj = 0; jj < 4; jj++)
                vv[jj] = *(const float4*)(Vbase + (size_t)(k0 + j0 + jj) * HD_ + d0);
            const float* vf = (const float*)vv;
            #pragma unroll
            for (int dd = 0; dd < 4; dd++) {
                float f[4] = {vf[0 * 4 + dd], vf[1 * 4 + dd], vf[2 * 4 + dd], vf[3 * 4 + dd]};
                uint2 hi, lo;
                split4(f, &hi, &lo);
                uint32_t off = (uint32_t)((d0 + dd) * VT_PITCH + j0 * 2);
                *(uint2*)(smc + F_VHI + off) = hi;
                *(uint2*)(smc + F_VLO + off) = lo;
            }
        }
        __syncthreads();

        float s[8][4];
        #pragma unroll
        for (int t = 0; t < 8; t++)
            #pragma unroll
            for (int e = 0; e < 4; e++) s[t][e] = 0.f;

        #pragma unroll
        for (int ks = 0; ks < 4; ks++) {
            uint32_t ah[4], al[4];
            {
                uint32_t byte = (uint32_t)((w * 16 + a_m) * 128 + ks * 32 + a_kb);
                uint32_t ad = smb + F_QHI + sw128(byte);
                ldsm_x4(ah, ad);
                ldsm_x4(al, ad + 16384);
            }
            uint32_t bfh[4][4], bfl[4][4];
            #pragma unroll
            for (int bt = 0; bt < 4; bt++) {
                uint32_t byte = (uint32_t)((bt * 16 + b_n) * 128 + ks * 32 + b_kb);
                uint32_t bd = smb + F_KHI + sw128(byte);
                ldsm_x4(bfh[bt], bd);
                ldsm_x4(bfl[bt], bd + 8192);
            }
            #pragma unroll
            for (int t = 0; t < 8; t++) {
                const uint32_t* bh = &bfh[t >> 1][(t & 1) * 2];
                const uint32_t* bl = &bfl[t >> 1][(t & 1) * 2];
                mma_f16(s[t], ah, bh);
                mma_f16(s[t], ah, bl);
                mma_f16(s[t], al, bh);
            }
        }

        const int r0g = q0 + w * 16 + g;
        const bool need_mask = (k0 + 64 > q0 + w * 16);
        #pragma unroll
        for (int t = 0; t < 8; t++) {
            int jc = k0 + t * 8 + q * 2;
            #pragma unroll
            for (int e = 0; e < 4; e++) {
                int row = r0g + (e >> 1) * 8;
                int col = jc + (e & 1);
                float v = s[t][e] * 0.125f;
                if (need_mask && col > row) v = -1e30f;
                s[t][e] = v;
            }
        }

        float mnew[2] = {-1e30f, -1e30f};
        #pragma unroll
        for (int t = 0; t < 8; t++) {
            mnew[0] = fmaxf(mnew[0], fmaxf(s[t][0], s[t][1]));
            mnew[1] = fmaxf(mnew[1], fmaxf(s[t][2], s[t][3]));
        }
        #pragma unroll
        for (int off = 1; off < 4; off <<= 1) {
            mnew[0] = fmaxf(mnew[0], __shfl_xor_sync(0xffffffffu, mnew[0], off));
            mnew[1] = fmaxf(mnew[1], __shfl_xor_sync(0xffffffffu, mnew[1], off));
        }
        float ms[2], sum[2] = {0.f, 0.f};
        #pragma unroll
        for (int r = 0; r < 2; r++) {
            mnew[r] = fmaxf(m_st[r], mnew[r]);
            ms[r] = __expf(m_st[r] - mnew[r]);
            m_st[r] = mnew[r];
        }
        #pragma unroll
        for (int t = 0; t < 8; t++) {
            s[t][0] = __expf(s[t][0] - mnew[0]);
            s[t][1] = __expf(s[t][1] - mnew[0]);
            s[t][2] = __expf(s[t][2] - mnew[1]);
            s[t][3] = __expf(s[t][3] - mnew[1]);
            sum[0] += s[t][0] + s[t][1];
            sum[1] += s[t][2] + s[t][3];
        }
        #pragma unroll
        for (int off = 1; off < 4; off <<= 1) {
            sum[0] += __shfl_xor_sync(0xffffffffu, sum[0], off);
            sum[1] += __shfl_xor_sync(0xffffffffu, sum[1], off);
        }
        l_st[0] = l_st[0] * ms[0] + sum[0];
        l_st[1] = l_st[1] * ms[1] + sum[1];

        #pragma unroll
        for (int t = 0; t < 8; t++) {
            o[t][0] *= ms[0]; o[t][1] *= ms[0];
            o[t][2] *= ms[1]; o[t][3] *= ms[1];
        }

        #pragma unroll
        for (int ks = 0; ks < 4; ks++) {
            uint32_t ph[4], pl[4];
            {
                const float* t0 = s[2 * ks];
                const float* t1 = s[2 * ks + 1];
                ph[0] = packh2(t0[0], t0[1]);
                ph[1] = packh2(t0[2], t0[3]);
                ph[2] = packh2(t1[0], t1[1]);
                ph[3] = packh2(t1[2], t1[3]);
                pl[0] = packh2(h2lo_res(ph[0], t0[0]), t0[1] - __half2float(__ushort_as_half((unsigned short)(ph[0] >> 16))));
                pl[1] = packh2(h2lo_res(ph[1], t0[2]), t0[3] - __half2float(__ushort_as_half((unsigned short)(ph[1] >> 16))));
                pl[2] = packh2(h2lo_res(ph[2], t1[0]), t1[1] - __half2float(__ushort_as_half((unsigned short)(ph[2] >> 16))));
                pl[3] = packh2(h2lo_res(ph[3], t1[2]), t1[3] - __half2float(__ushort_as_half((unsigned short)(ph[3] >> 16))));
            }
            uint32_t vfh[4][4], vfl[4][4];
            #pragma unroll
            for (int bt = 0; bt < 4; bt++) {
                uint32_t off = (uint32_t)((bt * 16 + v_row) * VT_PITCH + ks * 32 + v_cb);
                ldsm_x4(vfh[bt], smb + F_VHI + off);
                ldsm_x4(vfl[bt], smb + F_VLO + off);
            }
            #pragma unroll
            for (int t = 0; t < 8; t++) {
                const uint32_t* bh = &vfh[t >> 1][(t & 1) * 2];
                const uint32_t* bl = &vfl[t >> 1][(t & 1) * 2];
                mma_f16(o[t], ph, bh);
                mma_f16(o[t], ph, bl);
                mma_f16(o[t], pl, bh);
            }
        }
    }

    const int b = bh >> 4;
    const int h = bh & 15;
    const float inv0 = 1.f / l_st[0];
    const float inv1 = 1.f / l_st[1];
    #pragma unroll
    for (int t = 0; t < 8; t++) {
        int dc = t * 8 + q * 2;
        int gs0 = q0 + w * 16 + g;
        *(float2*)(Out + ((size_t)(b * S_ + gs0)) * D_ + h * 64 + dc) =
            make_float2(o[t][0] * inv0, o[t][1] * inv0);
        *(float2*)(Out + ((size_t)(b * S_ + gs0 + 8)) * D_ + h * 64 + dc) =
            make_float2(o[t][2] * inv1, o[t][3] * inv1);
    }
}

// ============================================================================
// Launch
// ============================================================================
extern "C" void kernel_launch(void* const* d_in, const int* in_sizes, int n_in,
                              void* d_out, int out_size)
{
    const float* q  = (const float*)d_in[0];
    const float* k  = (const float*)d_in[1];
    const float* v  = (const float*)d_in[2];
    const float* Wq = (const float*)d_in[4];
    const float* bq = (const float*)d_in[5];
    const float* Wk = (const float*)d_in[6];
    const float* bk = (const float*)d_in[7];
    const float* Wv = (const float*)d_in[8];
    const float* bv = (const float*)d_in[9];
    const float* Wo = (const float*)d_in[10];
    const float* bo = (const float*)d_in[11];

    float* out = (float*)d_out;
    float* kh  = out + OUT_ELEMS;
    float* vh  = out + 2 * OUT_ELEMS;

    float* qh;   cudaGetSymbolAddress((void**)&qh,   g_qh);
    float* attn; cudaGetSymbolAddress((void**)&attn, g_attn);

    cudaFuncSetAttribute(gemm_hmma_kernel,
                         cudaFuncAttributeMaxDynamicSharedMemorySize, GEMM_SMEM);
    cudaFuncSetAttribute(flash_kernel,
                         cudaFuncAttributeMaxDynamicSharedMemorySize, FLASH_SMEM);

    dim3 qkv_grid(D_ / 128, M_ / 128, 3);
    gemm_hmma_kernel<<<qkv_grid, 512, GEMM_SMEM>>>(
        q, k, v, Wq, Wk, Wv, bq, bk, bv, qh, kh, vh, 1);

    flash_kernel<<<dim3(S_ / 128, B_ * H_), 256, FLASH_SMEM>>>(qh, kh, vh, attn);

    dim3 o_grid(D_ / 128, M_ / 128, 1);
    gemm_hmma_kernel<<<o_grid, 512, GEMM_SMEM>>>(
        attn, attn, attn, Wo, Wo, Wo, bo, bo, bo, out, out, out, 0);
}